// round 10
// baseline (speedup 1.0000x reference)
#include <cuda_runtime.h>
#include <math.h>

#define Bn   2
#define Sn   2048
#define En   512
#define Hn   8
#define DHn  64
#define HIDn 2048
#define OUTn 6
#define Wn   5
#define SKn  2044          // S - W + 1
#define BSn  (Bn*Sn)       // 4096
#define NBH  (Bn*Hn)       // 16
#define NCHUNK 128
#define QB   124           // queries per CTA
#define NQB  17            // ceil(2048/124)
#define KT   60            // keys owned per tile iteration (64 raw cols)
#define NTC  35            // ceil(2044/60)

typedef unsigned long long u64;

// ---------------- packed fp32x2 helpers (Blackwell FFMA2) --------------------
__device__ __forceinline__ u64 pk2(float lo, float hi) {
    u64 r;
    asm("mov.b64 %0, {%1, %2};" : "=l"(r) : "f"(lo), "f"(hi));
    return r;
}
__device__ __forceinline__ float2 upk2(u64 v) {
    float2 r;
    asm("mov.b64 {%0, %1}, %2;" : "=f"(r.x), "=f"(r.y) : "l"(v));
    return r;
}
__device__ __forceinline__ void ffma2(u64 &d, u64 a, u64 b) {
    asm("fma.rn.f32x2 %0, %1, %2, %0;" : "+l"(d) : "l"(a), "l"(b));
}
__device__ __forceinline__ void fmul2(u64 &d, u64 a) {
    asm("mul.rn.f32x2 %0, %0, %1;" : "+l"(d) : "l"(a));
}

// ---------------- scratch (static device globals; no runtime alloc) ----------
__device__ float g_x [BSn*En];
__device__ float g_x2[BSn*En];
__device__ float g_q [NBH*Sn*DHn];
__device__ float g_k [NBH*Sn*DHn];
__device__ float g_v [NBH*Sn*DHn];
__device__ float g_vs[NBH*SKn*DHn];
__device__ float g_h [BSn*HIDn];
__device__ float g_part[Bn*NCHUNK*OUTn];

// ---------------- embedding + positional encoding ----------------------------
__global__ void embed_kernel(const int* __restrict__ inputs,
                             const float* __restrict__ emb)
{
    int row = blockIdx.x;
    int s   = row % Sn;
    int tok = inputs[row];
    const float coef = -9.210340371976184f / (float)En;
    for (int e = threadIdx.x; e < En; e += blockDim.x) {
        float freq = expf((float)(e & ~1) * coef);
        float ang  = (float)s * freq;
        float pe   = (e & 1) ? cosf(ang) : sinf(ang);
        g_x[(size_t)row*En + e] = emb[(size_t)tok*En + e] + pe;
    }
}

// ---------------- fused QKV gemm (f32x2 core) ---------------------------------
struct QKVArgs {
    const float* W[3];
    const float* bias[3];
    float* out[3];
};

// shared 8x8-microtile inner step on packed accumulators
#define GEMM_STEP_F32X2(As_, Bs_, acc64_)                                     \
    {                                                                          \
        float4 a0 = *(const float4*)&As_[ty*4];                                \
        float4 a1 = *(const float4*)&As_[64 + ty*4];                           \
        float4 b0 = *(const float4*)&Bs_[tx*4];                                \
        float4 b1 = *(const float4*)&Bs_[64 + tx*4];                           \
        u64 bb0 = pk2(b0.x, b0.y), bb1 = pk2(b0.z, b0.w);                      \
        u64 bb2 = pk2(b1.x, b1.y), bb3 = pk2(b1.z, b1.w);                      \
        float av[8] = {a0.x,a0.y,a0.z,a0.w,a1.x,a1.y,a1.z,a1.w};               \
        _Pragma("unroll")                                                      \
        for (int i_ = 0; i_ < 8; i_++) {                                       \
            u64 aa = pk2(av[i_], av[i_]);                                      \
            ffma2(acc64_[i_][0], aa, bb0);                                     \
            ffma2(acc64_[i_][1], aa, bb1);                                     \
            ffma2(acc64_[i_][2], aa, bb2);                                     \
            ffma2(acc64_[i_][3], aa, bb3);                                     \
        }                                                                      \
    }

__global__ void __launch_bounds__(256, 2)
sgemm_qkv(const float* __restrict__ A, QKVArgs args)
{
    const int K = 512, N = 512;
    __shared__ float As[2][8][132];
    __shared__ float Bs[2][8][128];
    int z = blockIdx.z;
    const float* __restrict__ B    = args.W[z];
    const float* __restrict__ bias = args.bias[z];
    float* __restrict__ Cq         = args.out[z];

    int t  = threadIdx.x;
    int m0 = blockIdx.y * 128, n0 = blockIdx.x * 128;
    int ar = t >> 1, ac = (t & 1) * 4;
    int bk = t >> 5, bn = (t & 31) * 4;
    int tx = t & 15, ty = t >> 4;

    const float* Aptr = A + (size_t)(m0 + ar) * K + ac;
    const float* Bptr = B + (size_t)bk * N + n0 + bn;

    float4 ra = *(const float4*)Aptr;
    float4 rb = *(const float4*)Bptr;
    u64 acc64[8][4] = {};
    const int nk = K / 8;

    #pragma unroll 1
    for (int ks = 0; ks < nk; ks++) {
        int buf = ks & 1;
        As[buf][ac+0][ar] = ra.x;
        As[buf][ac+1][ar] = ra.y;
        As[buf][ac+2][ar] = ra.z;
        As[buf][ac+3][ar] = ra.w;
        *(float4*)&Bs[buf][bk][bn] = rb;
        __syncthreads();
        if (ks + 1 < nk) {
            ra = *(const float4*)(Aptr + (ks+1)*8);
            rb = *(const float4*)(Bptr + (size_t)(ks+1)*8*N);
        }
        #pragma unroll
        for (int k = 0; k < 8; k++) {
            GEMM_STEP_F32X2(As[buf][k], Bs[buf][k], acc64);
        }
        __syncthreads();
    }

    #pragma unroll
    for (int ig = 0; ig < 2; ig++)
    #pragma unroll
    for (int i = 0; i < 4; i++) {
        int r = m0 + ig*64 + ty*4 + i;
        int bq = r >> 11, s = r & 2047;
        #pragma unroll
        for (int jg = 0; jg < 2; jg++) {
            int c = n0 + jg*64 + tx*4;
            int h = c >> 6, d = c & 63;
            float2 p0 = upk2(acc64[ig*4+i][jg*2+0]);
            float2 p1 = upk2(acc64[ig*4+i][jg*2+1]);
            float4 o;
            o.x = p0.x + bias[c+0];
            o.y = p0.y + bias[c+1];
            o.z = p1.x + bias[c+2];
            o.w = p1.y + bias[c+3];
            *(float4*)&Cq[(((size_t)(bq*Hn + h))*Sn + s)*DHn + d] = o;
        }
    }
}

// ---------------- FFN gemm: mode 1 = bias+relu, mode 2 = bias+residual --------
__global__ void __launch_bounds__(256, 2)
sgemm_ffn(const float* __restrict__ A, const float* __restrict__ B,
          float* __restrict__ C, const float* __restrict__ bias,
          const float* __restrict__ res, int K, int N, int mode)
{
    __shared__ float As[2][8][132];
    __shared__ float Bs[2][8][128];
    int t  = threadIdx.x;
    int m0 = blockIdx.y * 128, n0 = blockIdx.x * 128;
    int ar = t >> 1, ac = (t & 1) * 4;
    int bk = t >> 5, bn = (t & 31) * 4;
    int tx = t & 15, ty = t >> 4;

    const float* Aptr = A + (size_t)(m0 + ar) * K + ac;
    const float* Bptr = B + (size_t)bk * N + n0 + bn;

    float4 ra = *(const float4*)Aptr;
    float4 rb = *(const float4*)Bptr;
    u64 acc64[8][4] = {};
    const int nk = K / 8;

    #pragma unroll 1
    for (int ks = 0; ks < nk; ks++) {
        int buf = ks & 1;
        As[buf][ac+0][ar] = ra.x;
        As[buf][ac+1][ar] = ra.y;
        As[buf][ac+2][ar] = ra.z;
        As[buf][ac+3][ar] = ra.w;
        *(float4*)&Bs[buf][bk][bn] = rb;
        __syncthreads();
        if (ks + 1 < nk) {
            ra = *(const float4*)(Aptr + (ks+1)*8);
            rb = *(const float4*)(Bptr + (size_t)(ks+1)*8*N);
        }
        #pragma unroll
        for (int k = 0; k < 8; k++) {
            GEMM_STEP_F32X2(As[buf][k], Bs[buf][k], acc64);
        }
        __syncthreads();
    }

    #pragma unroll
    for (int ig = 0; ig < 2; ig++)
    #pragma unroll
    for (int i = 0; i < 4; i++) {
        int r = m0 + ig*64 + ty*4 + i;
        #pragma unroll
        for (int jg = 0; jg < 2; jg++) {
            int c = n0 + jg*64 + tx*4;
            float2 p0 = upk2(acc64[ig*4+i][jg*2+0]);
            float2 p1 = upk2(acc64[ig*4+i][jg*2+1]);
            float4 o;
            o.x = p0.x + bias[c+0];
            o.y = p0.y + bias[c+1];
            o.z = p1.x + bias[c+2];
            o.w = p1.y + bias[c+3];
            if (mode == 1) {
                o.x = fmaxf(o.x, 0.f); o.y = fmaxf(o.y, 0.f);
                o.z = fmaxf(o.z, 0.f); o.w = fmaxf(o.w, 0.f);
            } else {
                const float4 rr = *(const float4*)&res[(size_t)r*N + c];
                o.x += rr.x; o.y += rr.y; o.z += rr.z; o.w += rr.w;
            }
            *(float4*)&C[(size_t)r*N + c] = o;
        }
    }
}

// ---------------- V window pre-sum -------------------------------------------
__global__ void vsum_kernel()
{
    int idx = blockIdx.x * 256 + threadIdx.x;
    if (idx >= NBH*SKn*DHn) return;
    int d  = idx % DHn;
    int t  = (idx / DHn) % SKn;
    int bh = idx / (DHn*SKn);
    const float* v = g_v + (size_t)bh * Sn * DHn;
    float s = 0.f;
    #pragma unroll
    for (int j = 0; j < Wn; j++) s += v[(size_t)(t + j)*DHn + d];
    g_vs[idx] = s;
}

// =============================================================================
// Fused attention (f32x2 core): 124-query tile, 60-key (64 raw) iterations
// =============================================================================
__device__ __forceinline__ int rowmap(int ty, int i) {
    return (i < 4) ? (ty*4 + i) : (64 + ty*4 + (i - 4));
}

#define SM_QS 0
#define SM_KS (64*132)
#define SM_VS (64*132 + 64*68)
#define SM_TT (64*132 + 2*64*68)
#define SM_FLOATS (64*132 + 2*64*68 + 132*68)   // 26128 floats = 104512 B

__global__ void __launch_bounds__(256, 2)
attn_fused()
{
    extern __shared__ float sm[];
    float* Qs = sm + SM_QS;      // [64 dims][132] : 128 q-halo rows, k-major
    float* Ks = sm + SM_KS;      // [64 dims][68]  : 64 raw key rows, k-major
    float* Vs = sm + SM_VS;      // [64 keys][68]  : row-major vsum
    float* Tt = sm + SM_TT;      // [132 qrows][68]: raw QK tile, reused as P

    int bh = blockIdx.y;
    int q0 = blockIdx.x * QB;
    const float* __restrict__ Q = g_q  + (size_t)bh*Sn*DHn;
    const float* __restrict__ K = g_k  + (size_t)bh*Sn*DHn;
    const float* __restrict__ V = g_vs + (size_t)bh*SKn*DHn;

    int t  = threadIdx.x;
    int tx = t & 15, ty = t >> 4;
    int lr = t >> 1, lc4 = (t & 1) * 4;    // Q-halo loader mapping
    int kr = t >> 2, kc = (t & 3) * 16;    // K/V loader mapping (64 rows)

    // ---- load Q halo once: global rows q0-2 .. q0+125, zero-padded ----
    {
        int gq = q0 - 2 + lr;
        bool ok = (gq >= 0 && gq < Sn);
        const float* qp = Q + (size_t)(ok ? gq : 0)*DHn;
        #pragma unroll
        for (int p = 0; p < 8; p++) {
            int c = p*8 + lc4;
            float4 v = make_float4(0.f,0.f,0.f,0.f);
            if (ok) v = *(const float4*)(qp + c);
            Qs[(c+0)*132 + lr] = v.x;
            Qs[(c+1)*132 + lr] = v.y;
            Qs[(c+2)*132 + lr] = v.z;
            Qs[(c+3)*132 + lr] = v.w;
        }
    }

    float m[8], l[8];
    u64 acc64[8][2];
    #pragma unroll
    for (int i = 0; i < 8; i++) {
        m[i] = -1e30f; l[i] = 0.f;
        acc64[i][0] = 0ULL; acc64[i][1] = 0ULL;
    }

    #pragma unroll 1
    for (int tc = 0; tc < NTC; tc++) {
        int t0 = tc * KT;
        __syncthreads();   // prev iter's Ks/Vs/Tt consumers done

        // ---- load K raw rows t0 .. t0+63 (transposed, zero-pad >= Sn) ----
        {
            int gk = t0 + kr;
            bool ok = (gk < Sn);
            const float* kp = K + (size_t)(ok ? gk : 0)*DHn + kc;
            #pragma unroll
            for (int p = 0; p < 4; p++) {
                float4 v = make_float4(0.f,0.f,0.f,0.f);
                if (ok) v = *(const float4*)(kp + p*4);
                int c = kc + p*4;
                Ks[(c+0)*68 + kr] = v.x;
                Ks[(c+1)*68 + kr] = v.y;
                Ks[(c+2)*68 + kr] = v.z;
                Ks[(c+3)*68 + kr] = v.w;
            }
        }
        // ---- load Vsum rows t0 .. t0+63 row-major (zero-pad >= SKn) ----
        {
            int gv = t0 + kr;
            bool ok = (gv < SKn);
            const float* vp = V + (size_t)(ok ? gv : 0)*DHn + kc;
            #pragma unroll
            for (int p = 0; p < 4; p++) {
                float4 v = make_float4(0.f,0.f,0.f,0.f);
                if (ok) v = *(const float4*)(vp + p*4);
                *(float4*)&Vs[kr*68 + kc + p*4] = v;
            }
        }
        __syncthreads();

        // ---- raw QK tile: 128 q-halo rows x 64 key cols (f32x2) ----
        u64 tacc2[8][2] = {};
        #pragma unroll 8
        for (int k = 0; k < 64; k++) {
            float4 a0 = *(const float4*)&Qs[k*132 + ty*4];
            float4 a1 = *(const float4*)&Qs[k*132 + 64 + ty*4];
            float4 b  = *(const float4*)&Ks[k*68 + tx*4];
            u64 bb0 = pk2(b.x, b.y), bb1 = pk2(b.z, b.w);
            float av[8] = {a0.x,a0.y,a0.z,a0.w,a1.x,a1.y,a1.z,a1.w};
            #pragma unroll
            for (int i = 0; i < 8; i++) {
                u64 aa = pk2(av[i], av[i]);
                ffma2(tacc2[i][0], aa, bb0);
                ffma2(tacc2[i][1], aa, bb1);
            }
        }
        #pragma unroll
        for (int i = 0; i < 8; i++) {
            float2 p0 = upk2(tacc2[i][0]);
            float2 p1 = upk2(tacc2[i][1]);
            float4 o; o.x = p0.x; o.y = p0.y; o.z = p1.x; o.w = p1.y;
            *(float4*)&Tt[rowmap(ty, i)*68 + tx*4] = o;
        }
        __syncthreads();

        // ---- window-sum + mask + online softmax ----
        int cb = tx*4;
        float pv[8][4];
        #pragma unroll
        for (int i = 0; i < 8; i++) {
            int q = rowmap(ty, i);
            float s4[4] = {0.f,0.f,0.f,0.f};
            if (q < QB) {
                #pragma unroll
                for (int w = 0; w < Wn; w++) {
                    const float* rp = &Tt[(q+w)*68 + cb];
                    float4 a = *(const float4*)rp;
                    float4 b = *(const float4*)(rp + 4);
                    float tv[8] = {a.x,a.y,a.z,a.w,b.x,b.y,b.z,b.w};
                    #pragma unroll
                    for (int j = 0; j < 4; j++) s4[j] += tv[w + j];
                }
            }
            #pragma unroll
            for (int j = 0; j < 4; j++) {
                int lt = cb + j;
                int gt = t0 + lt;
                s4[j] = (lt < KT && gt < SKn && q < QB) ? s4[j]*0.125f : -1e30f;
            }
            float r = fmaxf(fmaxf(s4[0], s4[1]), fmaxf(s4[2], s4[3]));
            #pragma unroll
            for (int o = 1; o < 16; o <<= 1)
                r = fmaxf(r, __shfl_xor_sync(0xffffffffu, r, o));
            float mn = fmaxf(m[i], r);
            float corr = __expf(m[i] - mn);
            float rs = 0.f;
            #pragma unroll
            for (int j = 0; j < 4; j++) {
                float e = __expf(s4[j] - mn);
                pv[i][j] = e;
                rs += e;
            }
            #pragma unroll
            for (int o = 1; o < 16; o <<= 1)
                rs += __shfl_xor_sync(0xffffffffu, rs, o);
            l[i] = l[i]*corr + rs;
            m[i] = mn;
            u64 cc = pk2(corr, corr);
            fmul2(acc64[i][0], cc);
            fmul2(acc64[i][1], cc);
        }
        __syncthreads();   // everyone done reading Tt

        // ---- write P into Tt ----
        #pragma unroll
        for (int i = 0; i < 8; i++) {
            float4 o;
            o.x = pv[i][0]; o.y = pv[i][1];
            o.z = pv[i][2]; o.w = pv[i][3];
            *(float4*)&Tt[rowmap(ty, i)*68 + tx*4] = o;
        }
        __syncthreads();

        // ---- acc += P @ Vs  (f32x2, k blocks of 4) ----
        #pragma unroll 3
        for (int kb = 0; kb < KT; kb += 4) {
            float4 b0 = *(const float4*)&Vs[(kb+0)*68 + tx*4];
            float4 b1 = *(const float4*)&Vs[(kb+1)*68 + tx*4];
            float4 b2 = *(const float4*)&Vs[(kb+2)*68 + tx*4];
            float4 b3 = *(const float4*)&Vs[(kb+3)*68 + tx*4];
            u64 b0p0 = pk2(b0.x,b0.y), b0p1 = pk2(b0.z,b0.w);
            u64 b1p0 = pk2(b1.x,b1.y), b1p1 = pk2(b1.z,b1.w);
            u64 b2p0 = pk2(b2.x,b2.y), b2p1 = pk2(b2.z,b2.w);
            u64 b3p0 = pk2(b3.x,b3.y), b3p1 = pk2(b3.z,b3.w);
            #pragma unroll
            for (int i = 0; i < 8; i++) {
                float4 p = *(const float4*)&Tt[rowmap(ty, i)*68 + kb];
                u64 px = pk2(p.x,p.x), py = pk2(p.y,p.y);
                u64 pz = pk2(p.z,p.z), pw = pk2(p.w,p.w);
                ffma2(acc64[i][0], px, b0p0); ffma2(acc64[i][1], px, b0p1);
                ffma2(acc64[i][0], py, b1p0); ffma2(acc64[i][1], py, b1p1);
                ffma2(acc64[i][0], pz, b2p0); ffma2(acc64[i][1], pz, b2p1);
                ffma2(acc64[i][0], pw, b3p0); ffma2(acc64[i][1], pw, b3p1);
            }
        }
    }

    // ---- normalize + scatter to g_x2[b, q, h*64+d] ----
    int b = bh >> 3, h = bh & 7;
    #pragma unroll
    for (int i = 0; i < 8; i++) {
        int q = rowmap(ty, i);
        int gq = q0 + q;
        if (q < QB && gq < Sn) {
            float inv = 1.f / l[i];
            float2 p0 = upk2(acc64[i][0]);
            float2 p1 = upk2(acc64[i][1]);
            float4 o;
            o.x = p0.x*inv; o.y = p0.y*inv;
            o.z = p1.x*inv; o.w = p1.y*inv;
            *(float4*)&g_x2[((size_t)(b*Sn) + gq)*En + h*DHn + tx*4] = o;
        }
    }
}

// ---------------- layernorm (E = 512) ----------------------------------------
__global__ void layernorm_kernel(const float* __restrict__ in,
                                 float* __restrict__ out,
                                 const float* __restrict__ w,
                                 const float* __restrict__ b)
{
    int row = blockIdx.x;
    int tid = threadIdx.x;
    const float* xr = in + (size_t)row * En;
    float v0 = xr[tid], v1 = xr[tid + 256];
    __shared__ float s1[256], s2[256];
    s1[tid] = v0 + v1;
    s2[tid] = v0*v0 + v1*v1;
    __syncthreads();
    for (int o = 128; o > 0; o >>= 1) {
        if (tid < o) { s1[tid] += s1[tid+o]; s2[tid] += s2[tid+o]; }
        __syncthreads();
    }
    float mean = s1[0] * (1.f/En);
    float var  = s2[0] * (1.f/En) - mean*mean;
    float rstd = rsqrtf(var + 1e-5f);
    float* orow = out + (size_t)row * En;
    orow[tid]       = (v0 - mean) * rstd * w[tid]       + b[tid];
    orow[tid + 256] = (v1 - mean) * rstd * w[tid + 256] + b[tid + 256];
}

// ---------------- final projection x[B, S*E] @ out_w[S*E, 6] -----------------
__global__ void out_stage1(const float* __restrict__ out_w)
{
    int b = blockIdx.y, chunk = blockIdx.x;
    int tid = threadIdx.x;
    const int CH = Sn*En / NCHUNK;
    const float* xr = g_x + (size_t)b*Sn*En + (size_t)chunk*CH;
    const float* wr = out_w + (size_t)chunk*CH*OUTn;
    float acc[OUTn] = {};
    for (int i = tid; i < CH; i += 256) {
        float xv = xr[i];
        #pragma unroll
        for (int o = 0; o < OUTn; o++) acc[o] += xv * wr[(size_t)i*OUTn + o];
    }
    __shared__ float red[OUTn*256];
    #pragma unroll
    for (int o = 0; o < OUTn; o++) red[o*256 + tid] = acc[o];
    __syncthreads();
    for (int st = 128; st > 0; st >>= 1) {
        if (tid < st)
            #pragma unroll
            for (int o = 0; o < OUTn; o++)
                red[o*256 + tid] += red[o*256 + tid + st];
        __syncthreads();
    }
    if (tid < OUTn) g_part[(b*NCHUNK + chunk)*OUTn + tid] = red[tid*256];
}

__global__ void out_stage2(const float* __restrict__ out_b,
                           float* __restrict__ out)
{
    int tid = threadIdx.x;
    if (tid < Bn*OUTn) {
        int b = tid / OUTn, o = tid % OUTn;
        float s = out_b[o];
        for (int c = 0; c < NCHUNK; c++)
            s += g_part[(b*NCHUNK + c)*OUTn + o];
        out[tid] = s;
    }
}

// ---------------- driver ------------------------------------------------------
extern "C" void kernel_launch(void* const* d_in, const int* in_sizes, int n_in,
                              void* d_out, int out_size)
{
    const int*   inputs = (const int*)  d_in[0];
    const float* emb    = (const float*)d_in[1];
    const float* ln_w   = (const float*)d_in[2];
    const float* ln_b   = (const float*)d_in[3];
    const float* q_w    = (const float*)d_in[4];
    const float* q_b    = (const float*)d_in[5];
    const float* k_w    = (const float*)d_in[6];
    const float* k_b    = (const float*)d_in[7];
    const float* v_w    = (const float*)d_in[8];
    const float* v_b    = (const float*)d_in[9];
    const float* fc1_w  = (const float*)d_in[10];
    const float* fc1_b  = (const float*)d_in[11];
    const float* fc2_w  = (const float*)d_in[12];
    const float* fc2_b  = (const float*)d_in[13];
    const float* out_w  = (const float*)d_in[14];
    const float* out_b  = (const float*)d_in[15];
    float* out = (float*)d_out;

    float *px, *px2, *pq, *pk, *pv, *ph;
    cudaGetSymbolAddress((void**)&px,  g_x);
    cudaGetSymbolAddress((void**)&px2, g_x2);
    cudaGetSymbolAddress((void**)&pq,  g_q);
    cudaGetSymbolAddress((void**)&pk,  g_k);
    cudaGetSymbolAddress((void**)&pv,  g_v);
    cudaGetSymbolAddress((void**)&ph,  g_h);

    const int attn_smem = SM_FLOATS * 4;   // 104512 B -> 2 CTAs/SM
    cudaFuncSetAttribute(attn_fused,
                         cudaFuncAttributeMaxDynamicSharedMemorySize, attn_smem);

    embed_kernel<<<BSn, 256>>>(inputs, emb);

    QKVArgs qa;
    qa.W[0] = q_w;  qa.W[1] = k_w;  qa.W[2] = v_w;
    qa.bias[0] = q_b; qa.bias[1] = k_b; qa.bias[2] = v_b;
    qa.out[0] = pq; qa.out[1] = pk; qa.out[2] = pv;

    for (int l = 0; l < 6; l++) {
        sgemm_qkv<<<dim3(En/128, BSn/128, 3), 256>>>(px, qa);

        vsum_kernel<<<(NBH*SKn*DHn + 255)/256, 256>>>();
        attn_fused<<<dim3(NQB, NBH), 256, attn_smem>>>();

        layernorm_kernel<<<BSn, 256>>>(px2, px, ln_w, ln_b);

        sgemm_ffn<<<dim3(HIDn/128, BSn/128), 256>>>(px, fc1_w, ph, fc1_b,
                                                    nullptr, En, HIDn, 1);
        sgemm_ffn<<<dim3(En/128, BSn/128), 256>>>(ph, fc2_w, px2, fc2_b,
                                                  px, HIDn, En, 2);

        layernorm_kernel<<<BSn, 256>>>(px2, px, ln_w, ln_b);
    }

    out_stage1<<<dim3(NCHUNK, Bn), 256>>>(out_w);
    out_stage2<<<1, 32>>>(out_b, out);
}

// round 13
// speedup vs baseline: 1.0427x; 1.0427x over previous
#include <cuda_runtime.h>
#include <cuda_bf16.h>
#include <math.h>
#include <stdint.h>

#define Bn   2
#define Sn   2048
#define En   512
#define Hn   8
#define DHn  64
#define HIDn 2048
#define OUTn 6
#define Wn   5
#define SKn  2044          // S - W + 1
#define BSn  (Bn*Sn)       // 4096
#define NBH  (Bn*Hn)       // 16
#define NCHUNK 128
#define QB   124           // queries per CTA (attention)
#define NQB  17
#define KT   60
#define NTC  35

typedef unsigned long long u64;

// ---------------- packed fp32x2 helpers --------------------------------------
__device__ __forceinline__ u64 pk2(float lo, float hi) {
    u64 r; asm("mov.b64 %0, {%1, %2};" : "=l"(r) : "f"(lo), "f"(hi)); return r;
}
__device__ __forceinline__ float2 upk2(u64 v) {
    float2 r; asm("mov.b64 {%0, %1}, %2;" : "=f"(r.x), "=f"(r.y) : "l"(v)); return r;
}
__device__ __forceinline__ void ffma2(u64 &d, u64 a, u64 b) {
    asm("fma.rn.f32x2 %0, %1, %2, %0;" : "+l"(d) : "l"(a), "l"(b));
}
__device__ __forceinline__ void fmul2(u64 &d, u64 a) {
    asm("mul.rn.f32x2 %0, %0, %1;" : "+l"(d) : "l"(a));
}

// ---------------- smem / mma helpers -----------------------------------------
__device__ __forceinline__ uint32_t smem_u32(const void* p) {
    uint32_t a;
    asm("{ .reg .u64 t; cvta.to.shared.u64 t, %1; cvt.u32.u64 %0, t; }"
        : "=r"(a) : "l"(p));
    return a;
}
#define SWZ(x) ((x) ^ (((x) >> 3) & 0x70))

__device__ __forceinline__ void ldsm4(uint32_t addr, uint32_t* r) {
    asm volatile("ldmatrix.sync.aligned.m8n8.x4.shared.b16 {%0,%1,%2,%3}, [%4];"
        : "=r"(r[0]), "=r"(r[1]), "=r"(r[2]), "=r"(r[3]) : "r"(addr));
}
__device__ __forceinline__ void mma16816(float* d, const uint32_t* a,
                                         uint32_t b0, uint32_t b1) {
    asm volatile(
        "mma.sync.aligned.m16n8k16.row.col.f32.bf16.bf16.f32 "
        "{%0,%1,%2,%3}, {%4,%5,%6,%7}, {%8,%9}, {%0,%1,%2,%3};"
        : "+f"(d[0]), "+f"(d[1]), "+f"(d[2]), "+f"(d[3])
        : "r"(a[0]), "r"(a[1]), "r"(a[2]), "r"(a[3]), "r"(b0), "r"(b1));
}

// split fp32 pair -> bf16x2 hi + bf16x2 lo  (a ~= hi + lo)
__device__ __forceinline__ void split_pair(float a, float b, uint32_t &hi, uint32_t &lo) {
    __nv_bfloat162 h = __floats2bfloat162_rn(a, b);
    float2 hf = __bfloat1622float2(h);
    __nv_bfloat162 l = __floats2bfloat162_rn(a - hf.x, b - hf.y);
    hi = *reinterpret_cast<uint32_t*>(&h);
    lo = *reinterpret_cast<uint32_t*>(&l);
}

// ---------------- scratch -----------------------------------------------------
__device__ float g_x [BSn*En];
__device__ float g_x2[BSn*En];
__device__ float g_q [NBH*Sn*DHn];
__device__ float g_k [NBH*Sn*DHn];
__device__ float g_v [NBH*Sn*DHn];
__device__ float g_vs[NBH*SKn*DHn];
__device__ float g_h [BSn*HIDn];
__device__ float g_part[Bn*NCHUNK*OUTn];

// ---------------- embedding + positional encoding ----------------------------
__global__ void embed_kernel(const int* __restrict__ inputs,
                             const float* __restrict__ emb)
{
    int row = blockIdx.x;
    int s   = row % Sn;
    int tok = inputs[row];
    const float coef = -9.210340371976184f / (float)En;
    for (int e = threadIdx.x; e < En; e += blockDim.x) {
        float freq = expf((float)(e & ~1) * coef);
        float ang  = (float)s * freq;
        float pe   = (e & 1) ? cosf(ang) : sinf(ang);
        g_x[(size_t)row*En + e] = emb[(size_t)tok*En + e] + pe;
    }
}

// =============================================================================
// HMMA GEMM: C[4096,N] = A[4096,K] @ B[K,N], split-bf16 (3 mma passes), fp32 acc
// CTA 128x128, warps 2(m)x4(n) each 64x32, K chunks of 64, SW128 smem staging.
// mode: 0 = bias + QKV scatter, 1 = bias+relu, 2 = bias+residual
// =============================================================================
#define MM_SMEM_BYTES 66560

__global__ void __launch_bounds__(256)
mm_gemm(const float* __restrict__ A, const float* __restrict__ Bm,
        float* __restrict__ C, const float* __restrict__ bias,
        const float* __restrict__ res, int K, int N, int mode)
{
    extern __shared__ char smraw[];
    uint32_t sb = (smem_u32(smraw) + 1023) & ~1023u;
    const uint32_t AH = sb;
    const uint32_t AL = AH + 16384;
    const uint32_t BH = AL + 16384;
    const uint32_t BL = BH + 16384;

    int t = threadIdx.x;
    int warp = t >> 5, lane = t & 31;
    int n0 = blockIdx.x * 128, m0 = blockIdx.y * 128;
    int wm = (warp & 1) * 64, wn = (warp >> 1) * 32;

    float acc[4][4][4] = {};

    // staging maps
    int ar = t >> 1, ac = (t & 1) * 32;        // A: row, k-offset (elements)
    int kp = t & 31;                            // B: k-pair (rows 2kp, 2kp+1)
    int nb = (t >> 5) * 16;                     // B: 16 n-cols per warp

    const int nk = K / 64;
    #pragma unroll 1
    for (int tc = 0; tc < nk; tc++) {
        int k0 = tc * 64;
        if (tc > 0) __syncthreads();   // prior mma reads done

        // ---- stage A chunk [128 m][64 k] fp32 -> bf16 hi/lo, SW128 k-major --
        {
            const float* ap = A + (size_t)(m0 + ar) * K + k0 + ac;
            #pragma unroll
            for (int p = 0; p < 8; p++) {
                float4 v = *(const float4*)(ap + p * 4);
                uint32_t h0, l0, h1, l1;
                split_pair(v.x, v.y, h0, l0);
                split_pair(v.z, v.w, h1, l1);
                uint32_t off = SWZ((uint32_t)(ar * 128 + (ac + p * 4) * 2));
                asm volatile("st.shared.v2.b32 [%0], {%1, %2};"
                             :: "r"(AH + off), "r"(h0), "r"(h1) : "memory");
                asm volatile("st.shared.v2.b32 [%0], {%1, %2};"
                             :: "r"(AL + off), "r"(l0), "r"(l1) : "memory");
            }
        }
        // ---- stage B chunk [64 k][128 n] -> Bt[n][k] bf16 hi/lo, SW128 ------
        {
            const float* bp0 = Bm + (size_t)(k0 + 2 * kp) * N + n0 + nb;
            const float* bp1 = bp0 + N;
            #pragma unroll
            for (int j = 0; j < 4; j++) {
                float4 r0 = *(const float4*)(bp0 + j * 4);
                float4 r1 = *(const float4*)(bp1 + j * 4);
                float e0[4] = {r0.x, r0.y, r0.z, r0.w};
                float e1[4] = {r1.x, r1.y, r1.z, r1.w};
                #pragma unroll
                for (int e = 0; e < 4; e++) {
                    int n = nb + j * 4 + e;
                    uint32_t hi, lo;
                    split_pair(e0[e], e1[e], hi, lo);   // (k, k+1) packed
                    uint32_t off = SWZ((uint32_t)(n * 128 + kp * 4));
                    asm volatile("st.shared.b32 [%0], %1;"
                                 :: "r"(BH + off), "r"(hi) : "memory");
                    asm volatile("st.shared.b32 [%0], %1;"
                                 :: "r"(BL + off), "r"(lo) : "memory");
                }
            }
        }
        __syncthreads();

        // ---- 4 k16 steps: ldmatrix frags + 48 mma -----------------------
        #pragma unroll
        for (int ks = 0; ks < 4; ks++) {
            int kb = ks * 32;   // byte offset of k16 step within 128B row
            uint32_t ah[4][4], al[4][4];
            uint32_t arow = (uint32_t)((wm + (lane & 15)) * 128 + kb + (lane >> 4) * 16);
            #pragma unroll
            for (int mt = 0; mt < 4; mt++) {
                uint32_t off = SWZ(arow + (uint32_t)(mt * 16 * 128));
                ldsm4(AH + off, ah[mt]);
                ldsm4(AL + off, al[mt]);
            }
            uint32_t bh[2][4], bl[2][4];
            {
                int nrow = wn + (lane & 7) + ((lane >> 3) & 1) * 8;
                int kbb  = kb + (lane >> 4) * 16;
                #pragma unroll
                for (int g2 = 0; g2 < 2; g2++) {
                    uint32_t off = SWZ((uint32_t)((nrow + g2 * 16) * 128 + kbb));
                    ldsm4(BH + off, bh[g2]);
                    ldsm4(BL + off, bl[g2]);
                }
            }
            #pragma unroll
            for (int mt = 0; mt < 4; mt++)
            #pragma unroll
            for (int nt = 0; nt < 4; nt++) {
                int g = nt >> 1, lo = nt & 1;
                mma16816(acc[mt][nt], ah[mt], bh[g][lo], bh[g][lo + 2]);
                mma16816(acc[mt][nt], ah[mt], bl[g][lo], bl[g][lo + 2]);
                mma16816(acc[mt][nt], al[mt], bh[g][lo], bh[g][lo + 2]);
            }
        }
    }

    // ---- epilogue: D frag layout (d0,d1: row t/4, cols 2(t%4); d2,d3: +8row)
    int lr = lane >> 2;
    int lc = (lane & 3) * 2;
    #pragma unroll
    for (int mt = 0; mt < 4; mt++)
    #pragma unroll
    for (int half = 0; half < 2; half++) {
        int r = m0 + wm + mt * 16 + lr + half * 8;
        #pragma unroll
        for (int nt = 0; nt < 4; nt++) {
            int c = n0 + wn + nt * 8 + lc;
            float2 o;
            o.x = acc[mt][nt][half * 2 + 0] + bias[c];
            o.y = acc[mt][nt][half * 2 + 1] + bias[c + 1];
            if (mode == 1) {
                o.x = fmaxf(o.x, 0.f); o.y = fmaxf(o.y, 0.f);
                *(float2*)&C[(size_t)r * N + c] = o;
            } else if (mode == 2) {
                float2 rr = *(const float2*)&res[(size_t)r * N + c];
                o.x += rr.x; o.y += rr.y;
                *(float2*)&C[(size_t)r * N + c] = o;
            } else {
                int b = r >> 11, s = r & 2047;
                int h = c >> 6, d = c & 63;
                *(float2*)&C[(((size_t)(b * Hn + h)) * Sn + s) * DHn + d] = o;
            }
        }
    }
}

// ---------------- V window pre-sum -------------------------------------------
__global__ void vsum_kernel()
{
    int idx = blockIdx.x * 256 + threadIdx.x;
    if (idx >= NBH*SKn*DHn) return;
    int d  = idx % DHn;
    int t  = (idx / DHn) % SKn;
    int bh = idx / (DHn*SKn);
    const float* v = g_v + (size_t)bh * Sn * DHn;
    float s = 0.f;
    #pragma unroll
    for (int j = 0; j < Wn; j++) s += v[(size_t)(t + j)*DHn + d];
    g_vs[idx] = s;
}

// =============================================================================
// Fused attention (f32x2 core): 124-query tile, 60-key (64 raw) iterations
// =============================================================================
__device__ __forceinline__ int rowmap(int ty, int i) {
    return (i < 4) ? (ty*4 + i) : (64 + ty*4 + (i - 4));
}

#define SM_QS 0
#define SM_KS (64*132)
#define SM_VS (64*132 + 64*68)
#define SM_TT (64*132 + 2*64*68)
#define SM_FLOATS (64*132 + 2*64*68 + 132*68)   // 26128 floats = 104512 B

__global__ void __launch_bounds__(256, 2)
attn_fused()
{
    extern __shared__ float sm[];
    float* Qs = sm + SM_QS;
    float* Ks = sm + SM_KS;
    float* Vs = sm + SM_VS;
    float* Tt = sm + SM_TT;

    int bh = blockIdx.y;
    int q0 = blockIdx.x * QB;
    const float* __restrict__ Q = g_q  + (size_t)bh*Sn*DHn;
    const float* __restrict__ K = g_k  + (size_t)bh*Sn*DHn;
    const float* __restrict__ V = g_vs + (size_t)bh*SKn*DHn;

    int t  = threadIdx.x;
    int tx = t & 15, ty = t >> 4;
    int lr = t >> 1, lc4 = (t & 1) * 4;
    int kr = t >> 2, kc = (t & 3) * 16;

    {
        int gq = q0 - 2 + lr;
        bool ok = (gq >= 0 && gq < Sn);
        const float* qp = Q + (size_t)(ok ? gq : 0)*DHn;
        #pragma unroll
        for (int p = 0; p < 8; p++) {
            int c = p*8 + lc4;
            float4 v = make_float4(0.f,0.f,0.f,0.f);
            if (ok) v = *(const float4*)(qp + c);
            Qs[(c+0)*132 + lr] = v.x;
            Qs[(c+1)*132 + lr] = v.y;
            Qs[(c+2)*132 + lr] = v.z;
            Qs[(c+3)*132 + lr] = v.w;
        }
    }

    float m[8], l[8];
    u64 acc64[8][2];
    #pragma unroll
    for (int i = 0; i < 8; i++) {
        m[i] = -1e30f; l[i] = 0.f;
        acc64[i][0] = 0ULL; acc64[i][1] = 0ULL;
    }

    #pragma unroll 1
    for (int tc = 0; tc < NTC; tc++) {
        int t0 = tc * KT;
        __syncthreads();

        {
            int gk = t0 + kr;
            bool ok = (gk < Sn);
            const float* kp = K + (size_t)(ok ? gk : 0)*DHn + kc;
            #pragma unroll
            for (int p = 0; p < 4; p++) {
                float4 v = make_float4(0.f,0.f,0.f,0.f);
                if (ok) v = *(const float4*)(kp + p*4);
                int c = kc + p*4;
                Ks[(c+0)*68 + kr] = v.x;
                Ks[(c+1)*68 + kr] = v.y;
                Ks[(c+2)*68 + kr] = v.z;
                Ks[(c+3)*68 + kr] = v.w;
            }
        }
        {
            int gv = t0 + kr;
            bool ok = (gv < SKn);
            const float* vp = V + (size_t)(ok ? gv : 0)*DHn + kc;
            #pragma unroll
            for (int p = 0; p < 4; p++) {
                float4 v = make_float4(0.f,0.f,0.f,0.f);
                if (ok) v = *(const float4*)(vp + p*4);
                *(float4*)&Vs[kr*68 + kc + p*4] = v;
            }
        }
        __syncthreads();

        u64 tacc2[8][2] = {};
        #pragma unroll 8
        for (int k = 0; k < 64; k++) {
            float4 a0 = *(const float4*)&Qs[k*132 + ty*4];
            float4 a1 = *(const float4*)&Qs[k*132 + 64 + ty*4];
            float4 b  = *(const float4*)&Ks[k*68 + tx*4];
            u64 bb0 = pk2(b.x, b.y), bb1 = pk2(b.z, b.w);
            float av[8] = {a0.x,a0.y,a0.z,a0.w,a1.x,a1.y,a1.z,a1.w};
            #pragma unroll
            for (int i = 0; i < 8; i++) {
                u64 aa = pk2(av[i], av[i]);
                ffma2(tacc2[i][0], aa, bb0);
                ffma2(tacc2[i][1], aa, bb1);
            }
        }
        #pragma unroll
        for (int i = 0; i < 8; i++) {
            float2 p0 = upk2(tacc2[i][0]);
            float2 p1 = upk2(tacc2[i][1]);
            float4 o; o.x = p0.x; o.y = p0.y; o.z = p1.x; o.w = p1.y;
            *(float4*)&Tt[rowmap(ty, i)*68 + tx*4] = o;
        }
        __syncthreads();

        int cb = tx*4;
        float pv[8][4];
        #pragma unroll
        for (int i = 0; i < 8; i++) {
            int q = rowmap(ty, i);
            float s4[4] = {0.f,0.f,0.f,0.f};
            if (q < QB) {
                #pragma unroll
                for (int w = 0; w < Wn; w++) {
                    const float* rp = &Tt[(q+w)*68 + cb];
                    float4 a = *(const float4*)rp;
                    float4 b = *(const float4*)(rp + 4);
                    float tv[8] = {a.x,a.y,a.z,a.w,b.x,b.y,b.z,b.w};
                    #pragma unroll
                    for (int j = 0; j < 4; j++) s4[j] += tv[w + j];
                }
            }
            #pragma unroll
            for (int j = 0; j < 4; j++) {
                int lt = cb + j;
                int gt = t0 + lt;
                s4[j] = (lt < KT && gt < SKn && q < QB) ? s4[j]*0.125f : -1e30f;
            }
            float r = fmaxf(fmaxf(s4[0], s4[1]), fmaxf(s4[2], s4[3]));
            #pragma unroll
            for (int o = 1; o < 16; o <<= 1)
                r = fmaxf(r, __shfl_xor_sync(0xffffffffu, r, o));
            float mn = fmaxf(m[i], r);
            float corr = __expf(m[i] - mn);
            float rs = 0.f;
            #pragma unroll
            for (int j = 0; j < 4; j++) {
                float e = __expf(s4[j] - mn);
                pv[i][j] = e;
                rs += e;
            }
            #pragma unroll
            for (int o = 1; o < 16; o <<= 1)
                rs += __shfl_xor_sync(0xffffffffu, rs, o);
            l[i] = l[i]*corr + rs;
            m[i] = mn;
            u64 cc = pk2(corr, corr);
            fmul2(acc64[i][0], cc);
            fmul2(acc64[i][1], cc);
        }
        __syncthreads();

        #pragma unroll
        for (int i = 0; i < 8; i++) {
            float4 o;
            o.x = pv[i][0]; o.y = pv[i][1];
            o.z = pv[i][2]; o.w = pv[i][3];
            *(float4*)&Tt[rowmap(ty, i)*68 + tx*4] = o;
        }
        __syncthreads();

        #pragma unroll 3
        for (int kb = 0; kb < KT; kb += 4) {
            float4 b0 = *(const float4*)&Vs[(kb+0)*68 + tx*4];
            float4 b1 = *(const float4*)&Vs[(kb+1)*68 + tx*4];
            float4 b2 = *(const float4*)&Vs[(kb+2)*68 + tx*4];
            float4 b3 = *(const float4*)&Vs[(kb+3)*68 + tx*4];
            u64 b0p0 = pk2(b0.x,b0.y), b0p1 = pk2(b0.z,b0.w);
            u64 b1p0 = pk2(b1.x,b1.y), b1p1 = pk2(b1.z,b1.w);
            u64 b2p0 = pk2(b2.x,b2.y), b2p1 = pk2(b2.z,b2.w);
            u64 b3p0 = pk2(b3.x,b3.y), b3p1 = pk2(b3.z,b3.w);
            #pragma unroll
            for (int i = 0; i < 8; i++) {
                float4 p = *(const float4*)&Tt[rowmap(ty, i)*68 + kb];
                u64 px = pk2(p.x,p.x), py = pk2(p.y,p.y);
                u64 pz = pk2(p.z,p.z), pw = pk2(p.w,p.w);
                ffma2(acc64[i][0], px, b0p0); ffma2(acc64[i][1], px, b0p1);
                ffma2(acc64[i][0], py, b1p0); ffma2(acc64[i][1], py, b1p1);
                ffma2(acc64[i][0], pz, b2p0); ffma2(acc64[i][1], pz, b2p1);
                ffma2(acc64[i][0], pw, b3p0); ffma2(acc64[i][1], pw, b3p1);
            }
        }
    }

    int b = bh >> 3, h = bh & 7;
    #pragma unroll
    for (int i = 0; i < 8; i++) {
        int q = rowmap(ty, i);
        int gq = q0 + q;
        if (q < QB && gq < Sn) {
            float inv = 1.f / l[i];
            float2 p0 = upk2(acc64[i][0]);
            float2 p1 = upk2(acc64[i][1]);
            float4 o;
            o.x = p0.x*inv; o.y = p0.y*inv;
            o.z = p1.x*inv; o.w = p1.y*inv;
            *(float4*)&g_x2[((size_t)(b*Sn) + gq)*En + h*DHn + tx*4] = o;
        }
    }
}

// ---------------- layernorm (E = 512) ----------------------------------------
__global__ void layernorm_kernel(const float* __restrict__ in,
                                 float* __restrict__ out,
                                 const float* __restrict__ w,
                                 const float* __restrict__ b)
{
    int row = blockIdx.x;
    int tid = threadIdx.x;
    const float* xr = in + (size_t)row * En;
    float v0 = xr[tid], v1 = xr[tid + 256];
    __shared__ float s1[256], s2[256];
    s1[tid] = v0 + v1;
    s2[tid] = v0*v0 + v1*v1;
    __syncthreads();
    for (int o = 128; o > 0; o >>= 1) {
        if (tid < o) { s1[tid] += s1[tid+o]; s2[tid] += s2[tid+o]; }
        __syncthreads();
    }
    float mean = s1[0] * (1.f/En);
    float var  = s2[0] * (1.f/En) - mean*mean;
    float rstd = rsqrtf(var + 1e-5f);
    float* orow = out + (size_t)row * En;
    orow[tid]       = (v0 - mean) * rstd * w[tid]       + b[tid];
    orow[tid + 256] = (v1 - mean) * rstd * w[tid + 256] + b[tid + 256];
}

// ---------------- final projection x[B, S*E] @ out_w[S*E, 6] -----------------
__global__ void out_stage1(const float* __restrict__ out_w)
{
    int b = blockIdx.y, chunk = blockIdx.x;
    int tid = threadIdx.x;
    const int CH = Sn*En / NCHUNK;
    const float* xr = g_x + (size_t)b*Sn*En + (size_t)chunk*CH;
    const float* wr = out_w + (size_t)chunk*CH*OUTn;
    float acc[OUTn] = {};
    for (int i = tid; i < CH; i += 256) {
        float xv = xr[i];
        #pragma unroll
        for (int o = 0; o < OUTn; o++) acc[o] += xv * wr[(size_t)i*OUTn + o];
    }
    __shared__ float red[OUTn*256];
    #pragma unroll
    for (int o = 0; o < OUTn; o++) red[o*256 + tid] = acc[o];
    __syncthreads();
    for (int st = 128; st > 0; st >>= 1) {
        if (tid < st)
            #pragma unroll
            for (int o = 0; o < OUTn; o++)
                red[o*256 + tid] += red[o*256 + tid + st];
        __syncthreads();
    }
    if (tid < OUTn) g_part[(b*NCHUNK + chunk)*OUTn + tid] = red[tid*256];
}

__global__ void out_stage2(const float* __restrict__ out_b,
                           float* __restrict__ out)
{
    int tid = threadIdx.x;
    if (tid < Bn*OUTn) {
        int b = tid / OUTn, o = tid % OUTn;
        float s = out_b[o];
        for (int c = 0; c < NCHUNK; c++)
            s += g_part[(b*NCHUNK + c)*OUTn + o];
        out[tid] = s;
    }
}

// ---------------- driver ------------------------------------------------------
extern "C" void kernel_launch(void* const* d_in, const int* in_sizes, int n_in,
                              void* d_out, int out_size)
{
    const int*   inputs = (const int*)  d_in[0];
    const float* emb    = (const float*)d_in[1];
    const float* ln_w   = (const float*)d_in[2];
    const float* ln_b   = (const float*)d_in[3];
    const float* q_w    = (const float*)d_in[4];
    const float* q_b    = (const float*)d_in[5];
    const float* k_w    = (const float*)d_in[6];
    const float* k_b    = (const float*)d_in[7];
    const float* v_w    = (const float*)d_in[8];
    const float* v_b    = (const float*)d_in[9];
    const float* fc1_w  = (const float*)d_in[10];
    const float* fc1_b  = (const float*)d_in[11];
    const float* fc2_w  = (const float*)d_in[12];
    const float* fc2_b  = (const float*)d_in[13];
    const float* out_w  = (const float*)d_in[14];
    const float* out_b  = (const float*)d_in[15];
    float* out = (float*)d_out;

    float *px, *px2, *pq, *pk, *pv, *ph;
    cudaGetSymbolAddress((void**)&px,  g_x);
    cudaGetSymbolAddress((void**)&px2, g_x2);
    cudaGetSymbolAddress((void**)&pq,  g_q);
    cudaGetSymbolAddress((void**)&pk,  g_k);
    cudaGetSymbolAddress((void**)&pv,  g_v);
    cudaGetSymbolAddress((void**)&ph,  g_h);

    const int attn_smem = SM_FLOATS * 4;
    cudaFuncSetAttribute(attn_fused,
                         cudaFuncAttributeMaxDynamicSharedMemorySize, attn_smem);
    cudaFuncSetAttribute(mm_gemm,
                         cudaFuncAttributeMaxDynamicSharedMemorySize, MM_SMEM_BYTES);

    embed_kernel<<<BSn, 256>>>(inputs, emb);

    for (int l = 0; l < 6; l++) {
        // QKV: three 4096x512x512 HMMA GEMMs with scatter epilogue
        mm_gemm<<<dim3(4, 32), 256, MM_SMEM_BYTES>>>(px, q_w, pq, q_b, nullptr, 512, 512, 0);
        mm_gemm<<<dim3(4, 32), 256, MM_SMEM_BYTES>>>(px, k_w, pk, k_b, nullptr, 512, 512, 0);
        mm_gemm<<<dim3(4, 32), 256, MM_SMEM_BYTES>>>(px, v_w, pv, v_b, nullptr, 512, 512, 0);

        vsum_kernel<<<(NBH*SKn*DHn + 255)/256, 256>>>();
        attn_fused<<<dim3(NQB, NBH), 256, attn_smem>>>();

        layernorm_kernel<<<BSn, 256>>>(px2, px, ln_w, ln_b);

        // FFN1: 4096x2048x512, relu
        mm_gemm<<<dim3(16, 32), 256, MM_SMEM_BYTES>>>(px, fc1_w, ph, fc1_b, nullptr, 512, 2048, 1);
        // FFN2: 4096x512x2048, residual
        mm_gemm<<<dim3(4, 32), 256, MM_SMEM_BYTES>>>(ph, fc2_w, px2, fc2_b, px, 2048, 512, 2);

        layernorm_kernel<<<BSn, 256>>>(px2, px, ln_w, ln_b);
    }

    out_stage1<<<dim3(NCHUNK, Bn), 256>>>(out_w);
    out_stage2<<<1, 32>>>(out_b, out);
}

// round 14
// speedup vs baseline: 1.1558x; 1.1084x over previous
#include <cuda_runtime.h>
#include <cuda_bf16.h>
#include <math.h>
#include <stdint.h>

#define Bn   2
#define Sn   2048
#define En   512
#define Hn   8
#define DHn  64
#define HIDn 2048
#define OUTn 6
#define Wn   5
#define SKn  2044          // S - W + 1
#define BSn  (Bn*Sn)       // 4096
#define NBH  (Bn*Hn)       // 16
#define NCHUNK 128
#define QB   124           // queries per CTA (attention)
#define NQB  17
#define KT   60
#define NTC  35

typedef unsigned long long u64;

// ---------------- packed fp32x2 helpers --------------------------------------
__device__ __forceinline__ u64 pk2(float lo, float hi) {
    u64 r; asm("mov.b64 %0, {%1, %2};" : "=l"(r) : "f"(lo), "f"(hi)); return r;
}
__device__ __forceinline__ float2 upk2(u64 v) {
    float2 r; asm("mov.b64 {%0, %1}, %2;" : "=f"(r.x), "=f"(r.y) : "l"(v)); return r;
}
__device__ __forceinline__ void ffma2(u64 &d, u64 a, u64 b) {
    asm("fma.rn.f32x2 %0, %1, %2, %0;" : "+l"(d) : "l"(a), "l"(b));
}
__device__ __forceinline__ void fmul2(u64 &d, u64 a) {
    asm("mul.rn.f32x2 %0, %0, %1;" : "+l"(d) : "l"(a));
}

// ---------------- smem / mma helpers -----------------------------------------
__device__ __forceinline__ uint32_t smem_u32(const void* p) {
    uint32_t a;
    asm("{ .reg .u64 t; cvta.to.shared.u64 t, %1; cvt.u32.u64 %0, t; }"
        : "=r"(a) : "l"(p));
    return a;
}
#define SWZ(x) ((x) ^ (((x) >> 3) & 0x70))

__device__ __forceinline__ void ldsm4(uint32_t addr, uint32_t* r) {
    asm volatile("ldmatrix.sync.aligned.m8n8.x4.shared.b16 {%0,%1,%2,%3}, [%4];"
        : "=r"(r[0]), "=r"(r[1]), "=r"(r[2]), "=r"(r[3]) : "r"(addr));
}
__device__ __forceinline__ void mma16816(float* d, const uint32_t* a,
                                         uint32_t b0, uint32_t b1) {
    asm volatile(
        "mma.sync.aligned.m16n8k16.row.col.f32.bf16.bf16.f32 "
        "{%0,%1,%2,%3}, {%4,%5,%6,%7}, {%8,%9}, {%0,%1,%2,%3};"
        : "+f"(d[0]), "+f"(d[1]), "+f"(d[2]), "+f"(d[3])
        : "r"(a[0]), "r"(a[1]), "r"(a[2]), "r"(a[3]), "r"(b0), "r"(b1));
}

// split fp32 pair -> bf16x2 hi + bf16x2 lo  (a ~= hi + lo)
__device__ __forceinline__ void split_pair(float a, float b, uint32_t &hi, uint32_t &lo) {
    __nv_bfloat162 h = __floats2bfloat162_rn(a, b);
    float2 hf = __bfloat1622float2(h);
    __nv_bfloat162 l = __floats2bfloat162_rn(a - hf.x, b - hf.y);
    hi = *reinterpret_cast<uint32_t*>(&h);
    lo = *reinterpret_cast<uint32_t*>(&l);
}

// ---------------- scratch -----------------------------------------------------
__device__ float g_x [BSn*En];
__device__ float g_x2[BSn*En];
__device__ float g_q [NBH*Sn*DHn];
__device__ float g_k [NBH*Sn*DHn];
__device__ float g_v [NBH*Sn*DHn];
__device__ float g_vs[NBH*SKn*DHn];
__device__ float g_h [BSn*HIDn];
__device__ float g_part[Bn*NCHUNK*OUTn];

// ---------------- embedding + positional encoding ----------------------------
__global__ void embed_kernel(const int* __restrict__ inputs,
                             const float* __restrict__ emb)
{
    int row = blockIdx.x;
    int s   = row % Sn;
    int tok = inputs[row];
    const float coef = -9.210340371976184f / (float)En;
    for (int e = threadIdx.x; e < En; e += blockDim.x) {
        float freq = expf((float)(e & ~1) * coef);
        float ang  = (float)s * freq;
        float pe   = (e & 1) ? cosf(ang) : sinf(ang);
        g_x[(size_t)row*En + e] = emb[(size_t)tok*En + e] + pe;
    }
}

// =============================================================================
// HMMA GEMM core: C[4096,N] = A[4096,K] @ B[K,N], split-bf16, fp32 acc
// mode: 0 = bias + QKV scatter, 1 = bias+relu, 2 = bias+residual
// =============================================================================
#define MM_SMEM_BYTES 66560

__device__ __forceinline__ void
mm_core(const float* __restrict__ A, const float* __restrict__ Bm,
        float* __restrict__ C, const float* __restrict__ bias,
        const float* __restrict__ res, int K, int N, int mode,
        int m0, int n0)
{
    extern __shared__ char smraw[];
    uint32_t sb = (smem_u32(smraw) + 1023) & ~1023u;
    const uint32_t AH = sb;
    const uint32_t AL = AH + 16384;
    const uint32_t BH = AL + 16384;
    const uint32_t BL = BH + 16384;

    int t = threadIdx.x;
    int warp = t >> 5, lane = t & 31;
    int wm = (warp & 1) * 64, wn = (warp >> 1) * 32;

    float acc[4][4][4] = {};

    int ar = t >> 1, ac = (t & 1) * 32;
    int kp = t & 31;
    int nb = (t >> 5) * 16;

    const int nk = K / 64;
    #pragma unroll 1
    for (int tc = 0; tc < nk; tc++) {
        int k0 = tc * 64;
        if (tc > 0) __syncthreads();

        {
            const float* ap = A + (size_t)(m0 + ar) * K + k0 + ac;
            #pragma unroll
            for (int p = 0; p < 8; p++) {
                float4 v = *(const float4*)(ap + p * 4);
                uint32_t h0, l0, h1, l1;
                split_pair(v.x, v.y, h0, l0);
                split_pair(v.z, v.w, h1, l1);
                uint32_t off = SWZ((uint32_t)(ar * 128 + (ac + p * 4) * 2));
                asm volatile("st.shared.v2.b32 [%0], {%1, %2};"
                             :: "r"(AH + off), "r"(h0), "r"(h1) : "memory");
                asm volatile("st.shared.v2.b32 [%0], {%1, %2};"
                             :: "r"(AL + off), "r"(l0), "r"(l1) : "memory");
            }
        }
        {
            const float* bp0 = Bm + (size_t)(k0 + 2 * kp) * N + n0 + nb;
            const float* bp1 = bp0 + N;
            #pragma unroll
            for (int j = 0; j < 4; j++) {
                float4 r0 = *(const float4*)(bp0 + j * 4);
                float4 r1 = *(const float4*)(bp1 + j * 4);
                float e0[4] = {r0.x, r0.y, r0.z, r0.w};
                float e1[4] = {r1.x, r1.y, r1.z, r1.w};
                #pragma unroll
                for (int e = 0; e < 4; e++) {
                    int n = nb + j * 4 + e;
                    uint32_t hi, lo;
                    split_pair(e0[e], e1[e], hi, lo);
                    uint32_t off = SWZ((uint32_t)(n * 128 + kp * 4));
                    asm volatile("st.shared.b32 [%0], %1;"
                                 :: "r"(BH + off), "r"(hi) : "memory");
                    asm volatile("st.shared.b32 [%0], %1;"
                                 :: "r"(BL + off), "r"(lo) : "memory");
                }
            }
        }
        __syncthreads();

        #pragma unroll
        for (int ks = 0; ks < 4; ks++) {
            int kb = ks * 32;
            uint32_t ah[4][4], al[4][4];
            uint32_t arow = (uint32_t)((wm + (lane & 15)) * 128 + kb + (lane >> 4) * 16);
            #pragma unroll
            for (int mt = 0; mt < 4; mt++) {
                uint32_t off = SWZ(arow + (uint32_t)(mt * 16 * 128));
                ldsm4(AH + off, ah[mt]);
                ldsm4(AL + off, al[mt]);
            }
            uint32_t bh[2][4], bl[2][4];
            {
                int nrow = wn + (lane & 7) + ((lane >> 3) & 1) * 8;
                int kbb  = kb + (lane >> 4) * 16;
                #pragma unroll
                for (int g2 = 0; g2 < 2; g2++) {
                    uint32_t off = SWZ((uint32_t)((nrow + g2 * 16) * 128 + kbb));
                    ldsm4(BH + off, bh[g2]);
                    ldsm4(BL + off, bl[g2]);
                }
            }
            #pragma unroll
            for (int mt = 0; mt < 4; mt++)
            #pragma unroll
            for (int nt = 0; nt < 4; nt++) {
                int g = nt >> 1, lo = nt & 1;
                mma16816(acc[mt][nt], ah[mt], bh[g][lo], bh[g][lo + 2]);
                mma16816(acc[mt][nt], ah[mt], bl[g][lo], bl[g][lo + 2]);
                mma16816(acc[mt][nt], al[mt], bh[g][lo], bh[g][lo + 2]);
            }
        }
    }

    int lr = lane >> 2;
    int lc = (lane & 3) * 2;
    #pragma unroll
    for (int mt = 0; mt < 4; mt++)
    #pragma unroll
    for (int half = 0; half < 2; half++) {
        int r = m0 + wm + mt * 16 + lr + half * 8;
        #pragma unroll
        for (int nt = 0; nt < 4; nt++) {
            int c = n0 + wn + nt * 8 + lc;
            float2 o;
            o.x = acc[mt][nt][half * 2 + 0] + bias[c];
            o.y = acc[mt][nt][half * 2 + 1] + bias[c + 1];
            if (mode == 1) {
                o.x = fmaxf(o.x, 0.f); o.y = fmaxf(o.y, 0.f);
                *(float2*)&C[(size_t)r * N + c] = o;
            } else if (mode == 2) {
                float2 rr = *(const float2*)&res[(size_t)r * N + c];
                o.x += rr.x; o.y += rr.y;
                *(float2*)&C[(size_t)r * N + c] = o;
            } else {
                int b = r >> 11, s = r & 2047;
                int h = c >> 6, d = c & 63;
                *(float2*)&C[(((size_t)(b * Hn + h)) * Sn + s) * DHn + d] = o;
            }
        }
    }
}

__global__ void __launch_bounds__(256)
mm_gemm(const float* __restrict__ A, const float* __restrict__ Bm,
        float* __restrict__ C, const float* __restrict__ bias,
        const float* __restrict__ res, int K, int N, int mode)
{
    mm_core(A, Bm, C, bias, res, K, N, mode,
            blockIdx.y * 128, blockIdx.x * 128);
}

struct QKVArgs {
    const float* W[3];
    const float* bias[3];
    float* out[3];
};

__global__ void __launch_bounds__(256)
mm_gemm_qkv(const float* __restrict__ A, QKVArgs args)
{
    int z = blockIdx.z;
    mm_core(A, args.W[z], args.out[z], args.bias[z], nullptr, 512, 512, 0,
            blockIdx.y * 128, blockIdx.x * 128);
}

// ---------------- V window pre-sum -------------------------------------------
__global__ void vsum_kernel()
{
    int idx = blockIdx.x * 256 + threadIdx.x;
    if (idx >= NBH*SKn*DHn) return;
    int d  = idx % DHn;
    int t  = (idx / DHn) % SKn;
    int bh = idx / (DHn*SKn);
    const float* v = g_v + (size_t)bh * Sn * DHn;
    float s = 0.f;
    #pragma unroll
    for (int j = 0; j < Wn; j++) s += v[(size_t)(t + j)*DHn + d];
    g_vs[idx] = s;
}

// =============================================================================
// Fused attention: HMMA QK phase (split-bf16) + fp32 softmax + FFMA2 PV
// 124-query tile, 60-key (64 raw) iterations.
// smem (bytes from 1024-aligned base):
//   QH 0..16K, QL 16K..32K : Q halo bf16 hi/lo [128 q][64 d] SW128
//   KH 32K..40K, KL 40K..48K : K tile bf16 hi/lo [64 key][64 d] SW128
//   VS 48K+1K=49152 : fp32 [64][68]
//   TT 66560 : fp32 [132][68] raw QK tile / P buffer
// =============================================================================
__device__ __forceinline__ int rowmap(int ty, int i) {
    return (i < 4) ? (ty*4 + i) : (64 + ty*4 + (i - 4));
}

#define AT_QH 0
#define AT_QL 16384
#define AT_KH 32768
#define AT_KL 40960
#define AT_VS 49152
#define AT_TT 66560
#define AT_BYTES (66560 + 35904 + 1024)   // 103488

__global__ void __launch_bounds__(256, 2)
attn_fused()
{
    extern __shared__ char smraw[];
    uint32_t s0 = smem_u32(smraw);
    uint32_t sb = (s0 + 1023) & ~1023u;
    char* base  = smraw + (sb - s0);
    const uint32_t QH = sb + AT_QH;
    const uint32_t QL = sb + AT_QL;
    const uint32_t KH = sb + AT_KH;
    const uint32_t KL = sb + AT_KL;
    float* Vs = (float*)(base + AT_VS);
    float* Tt = (float*)(base + AT_TT);

    int bh = blockIdx.y;
    int q0 = blockIdx.x * QB;
    const float* __restrict__ Q = g_q  + (size_t)bh*Sn*DHn;
    const float* __restrict__ K = g_k  + (size_t)bh*Sn*DHn;
    const float* __restrict__ V = g_vs + (size_t)bh*SKn*DHn;

    int t  = threadIdx.x;
    int warp = t >> 5, lane = t & 31;
    int tx = t & 15, ty = t >> 4;
    int lr = t >> 1, lc4 = (t & 1) * 4;    // Q loader: row, dim-group
    int kr = t >> 2, kc = (t & 3) * 16;    // K/V loader: row, dim-group

    // ---- stage Q halo once: rows q0-2 .. q0+125, bf16 hi/lo SW128 ----
    {
        int gq = q0 - 2 + lr;
        bool ok = (gq >= 0 && gq < Sn);
        const float* qp = Q + (size_t)(ok ? gq : 0)*DHn;
        #pragma unroll
        for (int p = 0; p < 8; p++) {
            int c = p*8 + lc4;
            float4 v = make_float4(0.f,0.f,0.f,0.f);
            if (ok) v = *(const float4*)(qp + c);
            uint32_t h0, l0, h1, l1;
            split_pair(v.x, v.y, h0, l0);
            split_pair(v.z, v.w, h1, l1);
            uint32_t off = SWZ((uint32_t)(lr * 128 + c * 2));
            asm volatile("st.shared.v2.b32 [%0], {%1, %2};"
                         :: "r"(QH + off), "r"(h0), "r"(h1) : "memory");
            asm volatile("st.shared.v2.b32 [%0], {%1, %2};"
                         :: "r"(QL + off), "r"(l0), "r"(l1) : "memory");
        }
    }

    float m[8], l[8];
    u64 acc64[8][2];
    #pragma unroll
    for (int i = 0; i < 8; i++) {
        m[i] = -1e30f; l[i] = 0.f;
        acc64[i][0] = 0ULL; acc64[i][1] = 0ULL;
    }

    #pragma unroll 1
    for (int tc = 0; tc < NTC; tc++) {
        int t0 = tc * KT;
        __syncthreads();   // prev iter readers of KH/KL/Vs/Tt done

        // ---- stage K tile [64 key][64 d] bf16 hi/lo (zero-pad >= Sn) ----
        {
            int gk = t0 + kr;
            bool ok = (gk < Sn);
            const float* kp = K + (size_t)(ok ? gk : 0)*DHn + kc;
            #pragma unroll
            for (int p = 0; p < 4; p++) {
                float4 v = make_float4(0.f,0.f,0.f,0.f);
                if (ok) v = *(const float4*)(kp + p*4);
                uint32_t h0, l0, h1, l1;
                split_pair(v.x, v.y, h0, l0);
                split_pair(v.z, v.w, h1, l1);
                uint32_t off = SWZ((uint32_t)(kr * 128 + (kc + p*4) * 2));
                asm volatile("st.shared.v2.b32 [%0], {%1, %2};"
                             :: "r"(KH + off), "r"(h0), "r"(h1) : "memory");
                asm volatile("st.shared.v2.b32 [%0], {%1, %2};"
                             :: "r"(KL + off), "r"(l0), "r"(l1) : "memory");
            }
        }
        // ---- stage Vsum rows fp32 (zero-pad >= SKn) ----
        {
            int gv = t0 + kr;
            bool ok = (gv < SKn);
            const float* vp = V + (size_t)(ok ? gv : 0)*DHn + kc;
            #pragma unroll
            for (int p = 0; p < 4; p++) {
                float4 v = make_float4(0.f,0.f,0.f,0.f);
                if (ok) v = *(const float4*)(vp + p*4);
                *(float4*)&Vs[kr*68 + kc + p*4] = v;
            }
        }
        __syncthreads();

        // ---- QK via HMMA: warp w -> T rows w*16..w*16+15, 64 cols --------
        {
            uint32_t arow = (uint32_t)((warp*16 + (lane & 15)) * 128 + (lane >> 4) * 16);
            int lr2 = lane >> 2, lc2 = (lane & 3) * 2;
            #pragma unroll
            for (int h = 0; h < 2; h++) {
                float tacc[4][4] = {};
                #pragma unroll
                for (int ks = 0; ks < 4; ks++) {
                    int kb = ks * 32;
                    uint32_t ah[4], al[4];
                    uint32_t aoff = SWZ(arow + (uint32_t)kb);
                    ldsm4(QH + aoff, ah);
                    ldsm4(QL + aoff, al);
                    uint32_t bhf[2][4], blf[2][4];
                    #pragma unroll
                    for (int g = 0; g < 2; g++) {
                        int nrow = h*32 + g*16 + (lane & 7) + ((lane >> 3) & 1) * 8;
                        uint32_t boff = SWZ((uint32_t)(nrow * 128 + kb + (lane >> 4) * 16));
                        ldsm4(KH + boff, bhf[g]);
                        ldsm4(KL + boff, blf[g]);
                    }
                    #pragma unroll
                    for (int nt = 0; nt < 4; nt++) {
                        int g = nt >> 1, lo = nt & 1;
                        mma16816(tacc[nt], ah, bhf[g][lo], bhf[g][lo + 2]);
                        mma16816(tacc[nt], ah, blf[g][lo], blf[g][lo + 2]);
                        mma16816(tacc[nt], al, bhf[g][lo], bhf[g][lo + 2]);
                    }
                }
                #pragma unroll
                for (int nt = 0; nt < 4; nt++) {
                    int c = h*32 + nt*8 + lc2;
                    *(float2*)&Tt[(warp*16 + lr2) * 68 + c] =
                        make_float2(tacc[nt][0], tacc[nt][1]);
                    *(float2*)&Tt[(warp*16 + lr2 + 8) * 68 + c] =
                        make_float2(tacc[nt][2], tacc[nt][3]);
                }
            }
        }
        __syncthreads();

        // ---- window-sum + mask + online softmax ----
        int cb = tx*4;
        float pv[8][4];
        #pragma unroll
        for (int i = 0; i < 8; i++) {
            int q = rowmap(ty, i);
            float s4[4] = {0.f,0.f,0.f,0.f};
            if (q < QB) {
                #pragma unroll
                for (int w = 0; w < Wn; w++) {
                    const float* rp = &Tt[(q+w)*68 + cb];
                    float4 a = *(const float4*)rp;
                    float4 b = *(const float4*)(rp + 4);
                    float tv[8] = {a.x,a.y,a.z,a.w,b.x,b.y,b.z,b.w};
                    #pragma unroll
                    for (int j = 0; j < 4; j++) s4[j] += tv[w + j];
                }
            }
            #pragma unroll
            for (int j = 0; j < 4; j++) {
                int lt = cb + j;
                int gt = t0 + lt;
                s4[j] = (lt < KT && gt < SKn && q < QB) ? s4[j]*0.125f : -1e30f;
            }
            float r = fmaxf(fmaxf(s4[0], s4[1]), fmaxf(s4[2], s4[3]));
            #pragma unroll
            for (int o = 1; o < 16; o <<= 1)
                r = fmaxf(r, __shfl_xor_sync(0xffffffffu, r, o));
            float mn = fmaxf(m[i], r);
            float corr = __expf(m[i] - mn);
            float rs = 0.f;
            #pragma unroll
            for (int j = 0; j < 4; j++) {
                float e = __expf(s4[j] - mn);
                pv[i][j] = e;
                rs += e;
            }
            #pragma unroll
            for (int o = 1; o < 16; o <<= 1)
                rs += __shfl_xor_sync(0xffffffffu, rs, o);
            l[i] = l[i]*corr + rs;
            m[i] = mn;
            u64 cc = pk2(corr, corr);
            fmul2(acc64[i][0], cc);
            fmul2(acc64[i][1], cc);
        }
        __syncthreads();

        // ---- write P into Tt ----
        #pragma unroll
        for (int i = 0; i < 8; i++) {
            float4 o;
            o.x = pv[i][0]; o.y = pv[i][1];
            o.z = pv[i][2]; o.w = pv[i][3];
            *(float4*)&Tt[rowmap(ty, i)*68 + tx*4] = o;
        }
        __syncthreads();

        // ---- acc += P @ Vs  (f32x2, k blocks of 4) ----
        #pragma unroll 3
        for (int kb = 0; kb < KT; kb += 4) {
            float4 b0 = *(const float4*)&Vs[(kb+0)*68 + tx*4];
            float4 b1 = *(const float4*)&Vs[(kb+1)*68 + tx*4];
            float4 b2 = *(const float4*)&Vs[(kb+2)*68 + tx*4];
            float4 b3 = *(const float4*)&Vs[(kb+3)*68 + tx*4];
            u64 b0p0 = pk2(b0.x,b0.y), b0p1 = pk2(b0.z,b0.w);
            u64 b1p0 = pk2(b1.x,b1.y), b1p1 = pk2(b1.z,b1.w);
            u64 b2p0 = pk2(b2.x,b2.y), b2p1 = pk2(b2.z,b2.w);
            u64 b3p0 = pk2(b3.x,b3.y), b3p1 = pk2(b3.z,b3.w);
            #pragma unroll
            for (int i = 0; i < 8; i++) {
                float4 p = *(const float4*)&Tt[rowmap(ty, i)*68 + kb];
                u64 px = pk2(p.x,p.x), py = pk2(p.y,p.y);
                u64 pz = pk2(p.z,p.z), pw = pk2(p.w,p.w);
                ffma2(acc64[i][0], px, b0p0); ffma2(acc64[i][1], px, b0p1);
                ffma2(acc64[i][0], py, b1p0); ffma2(acc64[i][1], py, b1p1);
                ffma2(acc64[i][0], pz, b2p0); ffma2(acc64[i][1], pz, b2p1);
                ffma2(acc64[i][0], pw, b3p0); ffma2(acc64[i][1], pw, b3p1);
            }
        }
    }

    int b = bh >> 3, h = bh & 7;
    #pragma unroll
    for (int i = 0; i < 8; i++) {
        int q = rowmap(ty, i);
        int gq = q0 + q;
        if (q < QB && gq < Sn) {
            float inv = 1.f / l[i];
            float2 p0 = upk2(acc64[i][0]);
            float2 p1 = upk2(acc64[i][1]);
            float4 o;
            o.x = p0.x*inv; o.y = p0.y*inv;
            o.z = p1.x*inv; o.w = p1.y*inv;
            *(float4*)&g_x2[((size_t)(b*Sn) + gq)*En + h*DHn + tx*4] = o;
        }
    }
}

// ---------------- layernorm (E = 512) ----------------------------------------
__global__ void layernorm_kernel(const float* __restrict__ in,
                                 float* __restrict__ out,
                                 const float* __restrict__ w,
                                 const float* __restrict__ b)
{
    int row = blockIdx.x;
    int tid = threadIdx.x;
    const float* xr = in + (size_t)row * En;
    float v0 = xr[tid], v1 = xr[tid + 256];
    __shared__ float s1[256], s2[256];
    s1[tid] = v0 + v1;
    s2[tid] = v0*v0 + v1*v1;
    __syncthreads();
    for (int o = 128; o > 0; o >>= 1) {
        if (tid < o) { s1[tid] += s1[tid+o]; s2[tid] += s2[tid+o]; }
        __syncthreads();
    }
    float mean = s1[0] * (1.f/En);
    float var  = s2[0] * (1.f/En) - mean*mean;
    float rstd = rsqrtf(var + 1e-5f);
    float* orow = out + (size_t)row * En;
    orow[tid]       = (v0 - mean) * rstd * w[tid]       + b[tid];
    orow[tid + 256] = (v1 - mean) * rstd * w[tid + 256] + b[tid + 256];
}

// ---------------- final projection x[B, S*E] @ out_w[S*E, 6] -----------------
__global__ void out_stage1(const float* __restrict__ out_w)
{
    int b = blockIdx.y, chunk = blockIdx.x;
    int tid = threadIdx.x;
    const int CH = Sn*En / NCHUNK;
    const float* xr = g_x + (size_t)b*Sn*En + (size_t)chunk*CH;
    const float* wr = out_w + (size_t)chunk*CH*OUTn;
    float acc[OUTn] = {};
    for (int i = tid; i < CH; i += 256) {
        float xv = xr[i];
        #pragma unroll
        for (int o = 0; o < OUTn; o++) acc[o] += xv * wr[(size_t)i*OUTn + o];
    }
    __shared__ float red[OUTn*256];
    #pragma unroll
    for (int o = 0; o < OUTn; o++) red[o*256 + tid] = acc[o];
    __syncthreads();
    for (int st = 128; st > 0; st >>= 1) {
        if (tid < st)
            #pragma unroll
            for (int o = 0; o < OUTn; o++)
                red[o*256 + tid] += red[o*256 + tid + st];
        __syncthreads();
    }
    if (tid < OUTn) g_part[(b*NCHUNK + chunk)*OUTn + tid] = red[tid*256];
}

__global__ void out_stage2(const float* __restrict__ out_b,
                           float* __restrict__ out)
{
    int tid = threadIdx.x;
    if (tid < Bn*OUTn) {
        int b = tid / OUTn, o = tid % OUTn;
        float s = out_b[o];
        for (int c = 0; c < NCHUNK; c++)
            s += g_part[(b*NCHUNK + c)*OUTn + o];
        out[tid] = s;
    }
}

// ---------------- driver ------------------------------------------------------
extern "C" void kernel_launch(void* const* d_in, const int* in_sizes, int n_in,
                              void* d_out, int out_size)
{
    const int*   inputs = (const int*)  d_in[0];
    const float* emb    = (const float*)d_in[1];
    const float* ln_w   = (const float*)d_in[2];
    const float* ln_b   = (const float*)d_in[3];
    const float* q_w    = (const float*)d_in[4];
    const float* q_b    = (const float*)d_in[5];
    const float* k_w    = (const float*)d_in[6];
    const float* k_b    = (const float*)d_in[7];
    const float* v_w    = (const float*)d_in[8];
    const float* v_b    = (const float*)d_in[9];
    const float* fc1_w  = (const float*)d_in[10];
    const float* fc1_b  = (const float*)d_in[11];
    const float* fc2_w  = (const float*)d_in[12];
    const float* fc2_b  = (const float*)d_in[13];
    const float* out_w  = (const float*)d_in[14];
    const float* out_b  = (const float*)d_in[15];
    float* out = (float*)d_out;

    float *px, *px2, *pq, *pk, *pv, *ph;
    cudaGetSymbolAddress((void**)&px,  g_x);
    cudaGetSymbolAddress((void**)&px2, g_x2);
    cudaGetSymbolAddress((void**)&pq,  g_q);
    cudaGetSymbolAddress((void**)&pk,  g_k);
    cudaGetSymbolAddress((void**)&pv,  g_v);
    cudaGetSymbolAddress((void**)&ph,  g_h);

    cudaFuncSetAttribute(attn_fused,
                         cudaFuncAttributeMaxDynamicSharedMemorySize, AT_BYTES);
    cudaFuncSetAttribute(mm_gemm,
                         cudaFuncAttributeMaxDynamicSharedMemorySize, MM_SMEM_BYTES);
    cudaFuncSetAttribute(mm_gemm_qkv,
                         cudaFuncAttributeMaxDynamicSharedMemorySize, MM_SMEM_BYTES);

    embed_kernel<<<BSn, 256>>>(inputs, emb);

    QKVArgs qa;
    qa.W[0] = q_w;  qa.W[1] = k_w;  qa.W[2] = v_w;
    qa.bias[0] = q_b; qa.bias[1] = k_b; qa.bias[2] = v_b;
    qa.out[0] = pq; qa.out[1] = pk; qa.out[2] = pv;

    for (int l = 0; l < 6; l++) {
        // QKV: batched 3x (4096x512x512) HMMA GEMMs with scatter epilogue
        mm_gemm_qkv<<<dim3(4, 32, 3), 256, MM_SMEM_BYTES>>>(px, qa);

        vsum_kernel<<<(NBH*SKn*DHn + 255)/256, 256>>>();
        attn_fused<<<dim3(NQB, NBH), 256, AT_BYTES>>>();

        layernorm_kernel<<<BSn, 256>>>(px2, px, ln_w, ln_b);

        // FFN1: 4096x2048x512, relu
        mm_gemm<<<dim3(16, 32), 256, MM_SMEM_BYTES>>>(px, fc1_w, ph, fc1_b, nullptr, 512, 2048, 1);
        // FFN2: 4096x512x2048, residual
        mm_gemm<<<dim3(4, 32), 256, MM_SMEM_BYTES>>>(ph, fc2_w, px2, fc2_b, px, 2048, 512, 2);

        layernorm_kernel<<<BSn, 256>>>(px2, px, ln_w, ln_b);
    }

    out_stage1<<<dim3(NCHUNK, Bn), 256>>>(out_w);
    out_stage2<<<1, 32>>>(out_b, out);
}